// round 15
// baseline (speedup 1.0000x reference)
#include <cuda_runtime.h>
#include <cuda_fp16.h>
#include <cstdint>
#include <math.h>

// ---------------- problem constants ----------------
#define B     4
#define N     8192
#define P     2048
#define C     128
#define COUT  256
#define S     32
#define R2    0.64f
#define EPSB  1e-5f

#define NQ    (B*P)          // 8192 queries
#define NG2   (NQ/2)         // 4096 groups of 2 queries (64 samples)
#define MLPCNT ((double)(B)*(double)(P)*(double)(S))

// smem layout (bytes). Pitch 304 B (152 halves): conflict-free ldmatrix.
// K: 0..127 feats, 128..130 xyz, 131..143 zero pad.
#define WPITCH  304
#define OFF_W   0                     // W fp16 [256][152]  77824 B
#define OFF_G   77824                 // 2 bufs x G[64][152] = 2 x 19456
#define GBUF    19456
#define SMEM_TOTAL (77824 + 2*19456)  // 116736

// ---------------- device scratch ----------------
__device__ float          d_newxyz[NQ * 3];
__device__ int            d_idx[NQ * S];
__device__ unsigned short d_fhi[(size_t)B * N * C];   // fp16 of featsT (B,N,C)
__device__ float          d_mx[NQ * COUT];
__device__ double         d_sums[2 * COUT];
__device__ double         d_sst[6];

// ---------------- PTX helpers ----------------
__device__ __forceinline__ uint32_t smem_u32(const void* p) {
    uint32_t a;
    asm("{ .reg .u64 t; cvta.to.shared.u64 t, %1; cvt.u32.u64 %0, t; }" : "=r"(a) : "l"(p));
    return a;
}
__device__ __forceinline__ void ldsm4(uint32_t* r, uint32_t addr) {
    asm volatile("ldmatrix.sync.aligned.m8n8.x4.shared.b16 {%0,%1,%2,%3}, [%4];"
                 : "=r"(r[0]), "=r"(r[1]), "=r"(r[2]), "=r"(r[3]) : "r"(addr));
}
__device__ __forceinline__ void mma16816(float* d, const uint32_t* a, const uint32_t* b) {
    asm volatile("mma.sync.aligned.m16n8k16.row.col.f32.f16.f16.f32 "
                 "{%0,%1,%2,%3}, {%4,%5,%6,%7}, {%8,%9}, {%0,%1,%2,%3};"
                 : "+f"(d[0]), "+f"(d[1]), "+f"(d[2]), "+f"(d[3])
                 : "r"(a[0]), "r"(a[1]), "r"(a[2]), "r"(a[3]), "r"(b[0]), "r"(b[1]));
}
__device__ __forceinline__ void cpa16(uint32_t dst, const void* src) {
    asm volatile("cp.async.cg.shared.global [%0], [%1], 16;" :: "r"(dst), "l"(src) : "memory");
}
#define CPASYNC_COMMIT() asm volatile("cp.async.commit_group;" ::: "memory")
#define CPASYNC_WAIT0()  asm volatile("cp.async.wait_group 0;" ::: "memory")

// ---------------- kernel 0: zero stats ----------------
__global__ void k_zero_stats() {
    int t = threadIdx.x;
    if (t < 2 * COUT) d_sums[t] = 0.0;
    if (t < 6)        d_sst[t]  = 0.0;
}

// ---------------- kernel 1: shift GEMM + BN stats ----------------
__global__ void k_shift_stats(const float* __restrict__ ffps,
                              const float* __restrict__ wsh) {
    int i = blockIdx.x * blockDim.x + threadIdx.x;
    float f0 = ffps[i*3+0], f1 = ffps[i*3+1], f2 = ffps[i*3+2];
    float xs[3], xq[3];
#pragma unroll
    for (int o = 0; o < 3; o++) {
        float x = wsh[o*3+0]*f0 + wsh[o*3+1]*f1 + wsh[o*3+2]*f2;
        xs[o] = x; xq[o] = x * x;
    }
#pragma unroll
    for (int off = 16; off > 0; off >>= 1) {
#pragma unroll
        for (int o = 0; o < 3; o++) {
            xs[o] += __shfl_down_sync(0xffffffffu, xs[o], off);
            xq[o] += __shfl_down_sync(0xffffffffu, xq[o], off);
        }
    }
    if ((threadIdx.x & 31) == 0) {
#pragma unroll
        for (int o = 0; o < 3; o++) {
            atomicAdd(&d_sst[o],   (double)xs[o]);
            atomicAdd(&d_sst[3+o], (double)xq[o]);
        }
    }
}

// ---------------- kernel 2: fused prep ----------------
// blocks [0, 1024): ball query (launched FIRST -> long scans start in wave 1)
// blocks [1024, 5120): feature transpose (streams behind / alongside)
__global__ void k_prep(const float* __restrict__ f,
                       const float* __restrict__ bxyz,
                       const float* __restrict__ ffps,
                       const float* __restrict__ wsh,
                       const float* __restrict__ gamma,
                       const float* __restrict__ beta) {
    if (blockIdx.x >= 1024) {
        // ---------- transpose part ----------
        __shared__ float tile[32][33];
        int bid = blockIdx.x - 1024;
        int tx = threadIdx.x & 31, ty = threadIdx.x >> 5;
        int b  = bid >> 10;
        int c0 = ((bid >> 8) & 3) * 32;
        int n0 = (bid & 255) * 32;
        const float* src = f + ((size_t)b * C + c0) * N + n0;
#pragma unroll
        for (int r = ty; r < 32; r += 8)
            tile[r][tx] = src[(size_t)r * N + tx];
        __syncthreads();
        size_t base = ((size_t)b * N + n0) * C + c0;
#pragma unroll
        for (int r = ty; r < 32; r += 8)
            d_fhi[base + (size_t)r * C + tx] =
                __half_as_ushort(__float2half_rn(tile[tx][r]));
        return;
    }

    // ---------- ball query part ----------
    int wid  = blockIdx.x * 8 + (threadIdx.x >> 5);
    int lane = threadIdx.x & 31;
    int b = wid >> 11;

    float cen[3];
    {
        const float* fp = ffps + (size_t)wid * 3;
        float f0 = fp[0], f1 = fp[1], f2 = fp[2];
        double cnt = (double)NQ;
#pragma unroll
        for (int o = 0; o < 3; o++) {
            float x = wsh[o*3+0]*f0 + wsh[o*3+1]*f1 + wsh[o*3+2]*f2;
            double m = d_sst[o] / cnt;
            double v = d_sst[3+o] / cnt - m * m;
            float a = gamma[o] * rsqrtf((float)v + EPSB);
            cen[o] = fmaxf((x - (float)m) * a + beta[o], 0.0f);
        }
    }
    if (lane == 0) {
        d_newxyz[wid*3+0] = cen[0];
        d_newxyz[wid*3+1] = cen[1];
        d_newxyz[wid*3+2] = cen[2];
    }

    int* outp = d_idx + (size_t)wid * S;

    // distance lower bound: points strictly inside [-1,1); cen >= 0
    {
        float e0 = fmaxf(cen[0] - 1.0f, 0.0f);
        float e1 = fmaxf(cen[1] - 1.0f, 0.0f);
        float e2 = fmaxf(cen[2] - 1.0f, 0.0f);
        if (e0*e0 + e1*e1 + e2*e2 >= R2) {
            if (lane < S) outp[lane] = 0;
            return;
        }
    }

    const float* xb = bxyz + (size_t)b * N * 3;
    int cnt = 0, first = 0;
    bool found = false;
    for (int n0 = 0; n0 < N && cnt < S; n0 += 128) {
        float d2v[4];
#pragma unroll
        for (int j = 0; j < 4; j++) {
            int n = n0 + j * 32 + lane;
            float dx = xb[n*3+0] - cen[0];
            float dy = xb[n*3+1] - cen[1];
            float dz = xb[n*3+2] - cen[2];
            d2v[j] = dx*dx + dy*dy + dz*dz;
        }
#pragma unroll
        for (int j = 0; j < 4; j++) {
            unsigned m = __ballot_sync(0xffffffffu, d2v[j] < R2);
            if (m) {
                if (!found) { found = true; first = n0 + j * 32 + __ffs(m) - 1; }
                bool hit = (m >> lane) & 1u;
                int pos = cnt + __popc(m & ((1u << lane) - 1u));
                if (hit && pos < S) outp[pos] = n0 + j * 32 + lane;
                cnt += __popc(m);
            }
        }
    }
    if (cnt > S) cnt = S;
    for (int s = cnt + lane; s < S; s += 32) outp[s] = first;
}

// ---- async gather of group gg into buffer pb ----
__device__ __forceinline__ void gather_async(uint32_t smb, char* smc,
                                             int gg, int pb,
                                             int warp, int lane, int t,
                                             const float* bxyz) {
    const int* idxp = d_idx + (size_t)gg * 64;
    int bb = gg >> 10;
    int l16 = lane & 15, hh = lane >> 4;
#pragma unroll
    for (int j = 0; j < 2; j++) {
        int s = warp * 4 + 2 * j + hh;
        int n = idxp[s];
        const char* src = (const char*)(d_fhi + ((size_t)bb * N + n) * C) + l16 * 16;
        cpa16(smb + OFF_G + (uint32_t)pb * GBUF + (uint32_t)s * WPITCH + (uint32_t)l16 * 16, src);
    }
    if (t < 64) {
        int n = idxp[t];
        int q = gg * 2 + (t >> 5);
        const float* cen = d_newxyz + (size_t)q * 3;
        const float* xp  = bxyz + ((size_t)bb * N + n) * 3;
        __half hx = __float2half_rn(xp[0] - cen[0]);
        __half hy = __float2half_rn(xp[1] - cen[1]);
        __half hz = __float2half_rn(xp[2] - cen[2]);
        char* dst = smc + OFF_G + (size_t)pb * GBUF + (size_t)t * WPITCH + 256;
        uint32_t xy = (uint32_t)__half_as_ushort(hx) |
                      ((uint32_t)__half_as_ushort(hy) << 16);
        *(uint32_t*)dst = xy;                   // k=128,129
        *(__half*)(dst + 4) = hz;               // k=130
    }
}

// ---- one group's MMA with interleaved epilogue slices of the previous group ----
// accN: this group's accumulators (32). accO: previous group's (read-only here).
// ah: hoisted A fragments for ks 0..2 (24 regs). ks 3..8 A loaded from smem.
// Epilogue slice at ks<8: 4 values of accO -> mxq/sums/sqs.
__device__ __forceinline__ void group_step(
    float* accN, const float* accO, bool do_epi,
    uint32_t bBase, const uint32_t* ah, uint32_t aHi0, uint32_t aHi1,
    float* mxq, float* sums, float* sqs)
{
#pragma unroll
    for (int j = 0; j < 32; j++) accN[j] = 0.f;
#pragma unroll
    for (int ks = 0; ks < 9; ks++) {
        uint32_t kb = (uint32_t)ks * 32;
        uint32_t bh[8], a8[8];
        const uint32_t *a0p, *a1p;
        ldsm4(&bh[0], bBase + kb);
        ldsm4(&bh[4], bBase + 16 * WPITCH + kb);
        if (ks < 3) {
            a0p = &ah[ks * 8];
            a1p = &ah[ks * 8 + 4];
        } else {
            ldsm4(&a8[0], aHi0 + kb);
            ldsm4(&a8[4], aHi1 + kb);
            a0p = &a8[0];
            a1p = &a8[4];
        }
#pragma unroll
        for (int m = 0; m < 2; m++) {
            const uint32_t* ap = m ? a1p : a0p;
#pragma unroll
            for (int n = 0; n < 4; n++) {
                int bi = 4 * (n >> 1) + 2 * (n & 1);
                mma16816(&accN[m * 16 + 4 * n], ap, &bh[bi]);
            }
        }
        // epilogue slice of previous group's acc (4 values per ks, ks<8)
        if (do_epi && ks < 8) {
            int kk = ks >> 1;                    // quad-row 0..3
            int m = kk >> 1, ds = kk & 1;
            int na0 = (ks & 1) * 2;              // na pair {0,1} or {2,3}
#pragma unroll
            for (int j = 0; j < 2; j++) {
                int na = na0 + j;
#pragma unroll
                for (int e = 0; e < 2; e++) {
                    float v = accO[m * 16 + na * 4 + ds * 2 + e];
                    mxq[kk] = fmaxf(mxq[kk], v);
                    sums[kk] += v;
                    sqs[kk] = fmaf(v, v, sqs[kk]);
                }
            }
        }
    }
}

// ---- shuffle-reduce mxq and store maxes for query group gp ----
__device__ __forceinline__ void epi_store(float* mxq, int gp, int wm, int wn, int lane) {
#pragma unroll
    for (int k = 0; k < 4; k++) {
        float mx = mxq[k];
        mx = fmaxf(mx, __shfl_xor_sync(0xffffffffu, mx, 1));
        mx = fmaxf(mx, __shfl_xor_sync(0xffffffffu, mx, 2));
        if ((lane & 3) == 0) {
            int o = wm * 32 + 16 * (k >> 1) + (lane >> 2) + 8 * (k & 1);
            d_mx[(size_t)(gp * 2 + wn) * COUT + o] = mx;
        }
    }
}

// ---- full (non-interleaved) epilogue for the final group ----
__device__ __forceinline__ void final_epi(const float* accO, int gp, int wm, int wn,
                                          int lane, float* sums, float* sqs) {
    float mxq[4] = {-INFINITY, -INFINITY, -INFINITY, -INFINITY};
#pragma unroll
    for (int k = 0; k < 4; k++) {
        int m = k >> 1, ds = k & 1;
#pragma unroll
        for (int na = 0; na < 4; na++)
#pragma unroll
            for (int e = 0; e < 2; e++) {
                float v = accO[m * 16 + na * 4 + ds * 2 + e];
                mxq[k] = fmaxf(mxq[k], v);
                sums[k] += v;
                sqs[k] = fmaf(v, v, sqs[k]);
            }
    }
    epi_store(mxq, gp, wm, wn, lane);
}

// ---------------- kernel 3: persistent HMMA MLP (512 threads, 16 warps) ----------------
// R12 tiling (wm 0..7 x wn 0..1, 64-sample groups, 2 smem buffers) with the epilogue
// of group g-1 interleaved into group g's MMA K-loop (ping-pong accumulators).
__global__ __launch_bounds__(512, 1)
void k_mlp(const float* __restrict__ bxyz, const float* __restrict__ wmlp) {
    extern __shared__ char smc[];
    uint32_t smb = smem_u32(smc);
    int t = threadIdx.x;
    int warp = t >> 5, lane = t & 31;
    int wm = warp & 7, wn = warp >> 3;

    // ---- zero W + G areas (pad columns must be 0) ----
    for (uint32_t off = (uint32_t)t * 16; off < SMEM_TOTAL; off += 512u * 16)
        *(uint4*)(smc + off) = make_uint4(0, 0, 0, 0);
    __syncthreads();

    // ---- W -> smem fp16, K-permuted: feats at 0..127, xyz at 128..130 ----
    for (int idx = t; idx < 256 * 131; idx += 512) {
        int o = idx / 131, k = idx % 131;
        int kk = (k < 3) ? (128 + k) : (k - 3);
        *(__half*)(smc + OFF_W + o * WPITCH + kk * 2) =
            __float2half_rn(wmlp[o * 131 + k]);
    }

    // ---- ldmatrix per-thread address components ----
    int sub = lane & 7, grp = lane >> 3;
    int rowA = sub + 8 * (grp & 1);  uint32_t kA2 = (uint32_t)(grp >> 1) * 16;
    int rowB = sub + 8 * (grp >> 1); uint32_t kB2 = (uint32_t)(grp & 1) * 16;
    uint32_t aHi0 = smb + OFF_W + (uint32_t)(wm * 32 + rowA) * WPITCH + kA2;
    uint32_t aHi1 = aHi0 + 16 * WPITCH;
    uint32_t bRow = (uint32_t)(wn * 32 + rowB) * WPITCH + kB2;

    // ---- prologue: async gather of first group into buffer 0 ----
    gather_async(smb, smc, blockIdx.x, 0, warp, lane, t, bxyz);
    CPASYNC_COMMIT();
    CPASYNC_WAIT0();
    __syncthreads();

    // ---- hoist A (W) fragments ks 0..2 into registers (24 regs) ----
    uint32_t ah[24];
#pragma unroll
    for (int ks = 0; ks < 3; ks++) {
        ldsm4(&ah[ks * 8 + 0], aHi0 + (uint32_t)ks * 32);
        ldsm4(&ah[ks * 8 + 4], aHi1 + (uint32_t)ks * 32);
    }

    float accA[32], accB[32];
    float sums[4] = {0.f, 0.f, 0.f, 0.f}, sqs[4] = {0.f, 0.f, 0.f, 0.f};

    int bid = blockIdx.x, gsz = gridDim.x;
    int cnt = (NG2 - 1 - bid) / gsz + 1;       // groups for this CTA

    for (int k = 0; k < cnt; k++) {
        int g = bid + k * gsz;
        int p = k & 1, pn = p ^ 1;

        // ---- issue next group's gather (lands during MMA) ----
        int gn = g + gsz;
        if (k + 1 < cnt) gather_async(smb, smc, gn, pn, warp, lane, t, bxyz);
        CPASYNC_COMMIT();

        uint32_t bBase = smb + OFF_G + (uint32_t)p * GBUF + bRow;
        float mxq[4] = {-INFINITY, -INFINITY, -INFINITY, -INFINITY};
        if (k & 1) group_step(accB, accA, k > 0, bBase, ah, aHi0, aHi1, mxq, sums, sqs);
        else       group_step(accA, accB, k > 0, bBase, ah, aHi0, aHi1, mxq, sums, sqs);
        if (k > 0) epi_store(mxq, g - gsz, wm, wn, lane);

        CPASYNC_WAIT0();
        __syncthreads();
    }
    // trailing epilogue for the last group
    if ((cnt - 1) & 1) final_epi(accB, bid + (cnt - 1) * gsz, wm, wn, lane, sums, sqs);
    else               final_epi(accA, bid + (cnt - 1) * gsz, wm, wn, lane, sums, sqs);

    // ---- flush channel sums ----
#pragma unroll
    for (int k = 0; k < 4; k++) {
        float s_ = sums[k], q_ = sqs[k];
        s_ += __shfl_xor_sync(0xffffffffu, s_, 1);
        s_ += __shfl_xor_sync(0xffffffffu, s_, 2);
        q_ += __shfl_xor_sync(0xffffffffu, q_, 1);
        q_ += __shfl_xor_sync(0xffffffffu, q_, 2);
        if ((lane & 3) == 0) {
            int o = wm * 32 + 16 * (k >> 1) + (lane >> 2) + 8 * (k & 1);
            atomicAdd(&d_sums[o],        (double)s_);
            atomicAdd(&d_sums[COUT + o], (double)q_);
        }
    }
}

// ---------------- kernel 4: finalize (affine computed in-block; gamma > 0) ----------
__global__ void k_finalize(const float* __restrict__ gamma,
                           const float* __restrict__ beta,
                           float* __restrict__ out) {
    __shared__ float aff[2 * COUT];
    int t = threadIdx.x;
    {
        double m = d_sums[t] / MLPCNT;
        double v = d_sums[COUT + t] / MLPCNT - m * m;
        float a  = gamma[t] * rsqrtf((float)v + EPSB);
        aff[t]        = a;
        aff[COUT + t] = beta[t] - (float)m * a;
    }
    __syncthreads();
    size_t i4 = (size_t)blockIdx.x * 256 + t;
    int o = (t * 4) & 255;
    float4 v = ((const float4*)d_mx)[i4];
    float4 r;
    r.x = fmaxf(aff[o+0] * v.x + aff[COUT+o+0], 0.0f);
    r.y = fmaxf(aff[o+1] * v.y + aff[COUT+o+1], 0.0f);
    r.z = fmaxf(aff[o+2] * v.z + aff[COUT+o+2], 0.0f);
    r.w = fmaxf(aff[o+3] * v.w + aff[COUT+o+3], 0.0f);
    ((float4*)out)[i4] = r;
}

// ---------------- launch ----------------
extern "C" void kernel_launch(void* const* d_in, const int* in_sizes, int n_in,
                              void* d_out, int out_size) {
    const float* ffps  = (const float*)d_in[0];
    const float* bxyz  = (const float*)d_in[1];
    const float* feats = (const float*)d_in[2];
    const float* wsh   = (const float*)d_in[3];
    const float* gsh   = (const float*)d_in[4];
    const float* bsh   = (const float*)d_in[5];
    const float* wmlp  = (const float*)d_in[6];
    const float* gmlp  = (const float*)d_in[7];
    const float* bmlp  = (const float*)d_in[8];
    float* out = (float*)d_out;

    cudaFuncSetAttribute(k_mlp, cudaFuncAttributeMaxDynamicSharedMemorySize, SMEM_TOTAL);

    k_zero_stats<<<1, 512>>>();
    k_shift_stats<<<NQ / 256, 256>>>(ffps, wsh);
    k_prep<<<4096 + NQ / 8, 256>>>(feats, bxyz, ffps, wsh, gsh, bsh);
    k_mlp<<<152, 512, SMEM_TOTAL>>>(bxyz, wmlp);
    k_finalize<<<NQ * COUT / 1024, 256>>>(gmlp, bmlp, out);
}

// round 16
// speedup vs baseline: 1.0741x; 1.0741x over previous
#include <cuda_runtime.h>
#include <cuda_fp16.h>
#include <cstdint>
#include <math.h>

// ---------------- problem constants ----------------
#define B     4
#define N     8192
#define P     2048
#define C     128
#define COUT  256
#define S     32
#define R2    0.64f
#define EPSB  1e-5f

#define NQ    (B*P)          // 8192 queries
#define NG2   (NQ/2)         // 4096 groups of 2 queries (64 samples)
#define MLPCNT ((double)(B)*(double)(P)*(double)(S))

// smem layout (bytes). Pitch 304 B (152 halves): conflict-free ldmatrix.
// K: 0..127 feats, 128..130 xyz, 131..143 zero pad.
#define WPITCH  304
#define OFF_W   0                     // W fp16 [256][152]  77824 B
#define OFF_G   77824                 // 2 bufs x G[64][152] = 2 x 19456
#define GBUF    19456
#define SMEM_TOTAL (77824 + 2*19456)  // 116736

// ---------------- device scratch ----------------
__device__ float          d_newxyz[NQ * 3];
__device__ int            d_idx[NQ * S];
__device__ unsigned short d_fhi[(size_t)B * N * C];   // fp16 of featsT (B,N,C)
__device__ float          d_mx[NQ * COUT];
__device__ double         d_sums[2 * COUT];
__device__ double         d_sst[6];

// ---------------- PTX helpers ----------------
__device__ __forceinline__ uint32_t smem_u32(const void* p) {
    uint32_t a;
    asm("{ .reg .u64 t; cvta.to.shared.u64 t, %1; cvt.u32.u64 %0, t; }" : "=r"(a) : "l"(p));
    return a;
}
__device__ __forceinline__ void ldsm4(uint32_t* r, uint32_t addr) {
    asm volatile("ldmatrix.sync.aligned.m8n8.x4.shared.b16 {%0,%1,%2,%3}, [%4];"
                 : "=r"(r[0]), "=r"(r[1]), "=r"(r[2]), "=r"(r[3]) : "r"(addr));
}
__device__ __forceinline__ void mma16816(float* d, const uint32_t* a, const uint32_t* b) {
    asm volatile("mma.sync.aligned.m16n8k16.row.col.f32.f16.f16.f32 "
                 "{%0,%1,%2,%3}, {%4,%5,%6,%7}, {%8,%9}, {%0,%1,%2,%3};"
                 : "+f"(d[0]), "+f"(d[1]), "+f"(d[2]), "+f"(d[3])
                 : "r"(a[0]), "r"(a[1]), "r"(a[2]), "r"(a[3]), "r"(b[0]), "r"(b[1]));
}
__device__ __forceinline__ void cpa16(uint32_t dst, const void* src) {
    asm volatile("cp.async.cg.shared.global [%0], [%1], 16;" :: "r"(dst), "l"(src) : "memory");
}
#define CPASYNC_COMMIT() asm volatile("cp.async.commit_group;" ::: "memory")
#define CPASYNC_WAIT0()  asm volatile("cp.async.wait_group 0;" ::: "memory")

// ---------------- kernel 0: zero stats ----------------
__global__ void k_zero_stats() {
    int t = threadIdx.x;
    if (t < 2 * COUT) d_sums[t] = 0.0;
    if (t < 6)        d_sst[t]  = 0.0;
}

// ---------------- kernel 1: shift GEMM + BN stats ----------------
__global__ void k_shift_stats(const float* __restrict__ ffps,
                              const float* __restrict__ wsh) {
    int i = blockIdx.x * blockDim.x + threadIdx.x;
    float f0 = ffps[i*3+0], f1 = ffps[i*3+1], f2 = ffps[i*3+2];
    float xs[3], xq[3];
#pragma unroll
    for (int o = 0; o < 3; o++) {
        float x = wsh[o*3+0]*f0 + wsh[o*3+1]*f1 + wsh[o*3+2]*f2;
        xs[o] = x; xq[o] = x * x;
    }
#pragma unroll
    for (int off = 16; off > 0; off >>= 1) {
#pragma unroll
        for (int o = 0; o < 3; o++) {
            xs[o] += __shfl_down_sync(0xffffffffu, xs[o], off);
            xq[o] += __shfl_down_sync(0xffffffffu, xq[o], off);
        }
    }
    if ((threadIdx.x & 31) == 0) {
#pragma unroll
        for (int o = 0; o < 3; o++) {
            atomicAdd(&d_sst[o],   (double)xs[o]);
            atomicAdd(&d_sst[3+o], (double)xq[o]);
        }
    }
}

// ---------------- kernel 2: fused prep ----------------
// blocks [0, 1024): ball query (launched FIRST -> long scans start in wave 1)
// blocks [1024, 2048): feature transpose, 128(N) x 32(C) tiles, float4 loads
__global__ void k_prep(const float* __restrict__ f,
                       const float* __restrict__ bxyz,
                       const float* __restrict__ ffps,
                       const float* __restrict__ wsh,
                       const float* __restrict__ gamma,
                       const float* __restrict__ beta) {
    if (blockIdx.x >= 1024) {
        // ---------- transpose part: (B,C,N) fp32 -> (B,N,C) fp16 ----------
        __shared__ float tile[32][133];      // pad 133: conflict-free col reads
        int bid = blockIdx.x - 1024;         // 0..1023 = 4(B) x 4(Cgrp) x 64(Ngrp)
        int lane = threadIdx.x & 31, warp = threadIdx.x >> 5;
        int b  = bid >> 8;
        int c0 = ((bid >> 6) & 3) * 32;
        int n0 = (bid & 63) * 128;
        const float* src = f + ((size_t)b * C + c0) * N + n0;
        // load: warp w covers c-rows {w, w+8, w+16, w+24}; 32 lanes x float4 = 128 n
#pragma unroll
        for (int r = warp; r < 32; r += 8) {
            float4 v = ((const float4*)(src + (size_t)r * N))[lane];
            tile[r][lane * 4 + 0] = v.x;
            tile[r][lane * 4 + 1] = v.y;
            tile[r][lane * 4 + 2] = v.z;
            tile[r][lane * 4 + 3] = v.w;
        }
        __syncthreads();
        // store: half-warp per n-row; lane handles channel pair -> half2
        size_t base = ((size_t)b * N + n0) * C + c0;
        int nn = warp * 2 + (lane >> 4);     // n offset within pass
        int cc = (lane & 15) * 2;
#pragma unroll
        for (int pass = 0; pass < 8; pass++) {
            int n = nn + pass * 16;
            __half2 h = __floats2half2_rn(tile[cc][n], tile[cc + 1][n]);
            *(__half2*)(d_fhi + base + (size_t)n * C + cc) = h;
        }
        return;
    }

    // ---------- ball query part ----------
    int wid  = blockIdx.x * 8 + (threadIdx.x >> 5);
    int lane = threadIdx.x & 31;
    int b = wid >> 11;

    float cen[3];
    {
        const float* fp = ffps + (size_t)wid * 3;
        float f0 = fp[0], f1 = fp[1], f2 = fp[2];
        double cnt = (double)NQ;
#pragma unroll
        for (int o = 0; o < 3; o++) {
            float x = wsh[o*3+0]*f0 + wsh[o*3+1]*f1 + wsh[o*3+2]*f2;
            double m = d_sst[o] / cnt;
            double v = d_sst[3+o] / cnt - m * m;
            float a = gamma[o] * rsqrtf((float)v + EPSB);
            cen[o] = fmaxf((x - (float)m) * a + beta[o], 0.0f);
        }
    }
    if (lane == 0) {
        d_newxyz[wid*3+0] = cen[0];
        d_newxyz[wid*3+1] = cen[1];
        d_newxyz[wid*3+2] = cen[2];
    }

    int* outp = d_idx + (size_t)wid * S;

    // distance lower bound: points strictly inside [-1,1); cen >= 0
    {
        float e0 = fmaxf(cen[0] - 1.0f, 0.0f);
        float e1 = fmaxf(cen[1] - 1.0f, 0.0f);
        float e2 = fmaxf(cen[2] - 1.0f, 0.0f);
        if (e0*e0 + e1*e1 + e2*e2 >= R2) {
            if (lane < S) outp[lane] = 0;
            return;
        }
    }

    const float* xb = bxyz + (size_t)b * N * 3;
    int cnt = 0, first = 0;
    bool found = false;
    for (int n0 = 0; n0 < N && cnt < S; n0 += 128) {
        float d2v[4];
#pragma unroll
        for (int j = 0; j < 4; j++) {
            int n = n0 + j * 32 + lane;
            float dx = xb[n*3+0] - cen[0];
            float dy = xb[n*3+1] - cen[1];
            float dz = xb[n*3+2] - cen[2];
            d2v[j] = dx*dx + dy*dy + dz*dz;
        }
#pragma unroll
        for (int j = 0; j < 4; j++) {
            unsigned m = __ballot_sync(0xffffffffu, d2v[j] < R2);
            if (m) {
                if (!found) { found = true; first = n0 + j * 32 + __ffs(m) - 1; }
                bool hit = (m >> lane) & 1u;
                int pos = cnt + __popc(m & ((1u << lane) - 1u));
                if (hit && pos < S) outp[pos] = n0 + j * 32 + lane;
                cnt += __popc(m);
            }
        }
    }
    if (cnt > S) cnt = S;
    for (int s = cnt + lane; s < S; s += 32) outp[s] = first;
}

// ---- async gather of group gg into buffer pb: features via cp.async,
// ---- recentered xyz fp16 into K-channels 128..130 via STS.
__device__ __forceinline__ void gather_async(uint32_t smb, char* smc,
                                             int gg, int pb,
                                             int warp, int lane, int t,
                                             const float* bxyz) {
    const int* idxp = d_idx + (size_t)gg * 64;
    int bb = gg >> 10;
    int l16 = lane & 15, hh = lane >> 4;
#pragma unroll
    for (int j = 0; j < 2; j++) {
        int s = warp * 4 + 2 * j + hh;
        int n = idxp[s];
        const char* src = (const char*)(d_fhi + ((size_t)bb * N + n) * C) + l16 * 16;
        cpa16(smb + OFF_G + (uint32_t)pb * GBUF + (uint32_t)s * WPITCH + (uint32_t)l16 * 16, src);
    }
    if (t < 64) {
        int n = idxp[t];
        int q = gg * 2 + (t >> 5);
        const float* cen = d_newxyz + (size_t)q * 3;
        const float* xp  = bxyz + ((size_t)bb * N + n) * 3;
        __half hx = __float2half_rn(xp[0] - cen[0]);
        __half hy = __float2half_rn(xp[1] - cen[1]);
        __half hz = __float2half_rn(xp[2] - cen[2]);
        char* dst = smc + OFF_G + (size_t)pb * GBUF + (size_t)t * WPITCH + 256;
        uint32_t xy = (uint32_t)__half_as_ushort(hx) |
                      ((uint32_t)__half_as_ushort(hy) << 16);
        *(uint32_t*)dst = xy;                   // k=128,129
        *(__half*)(dst + 4) = hz;               // k=130
    }
}

// ---------------- kernel 3: persistent HMMA MLP (512 threads, 16 warps) ----------------
// FROZEN R12 structure (measured 73 us x3): single-pass fp16, K=144 (9 K-steps),
// A ks 0..7 hoisted to regs, ks 8 from smem; epilogue max+sum+sumsq.
__global__ __launch_bounds__(512, 1)
void k_mlp(const float* __restrict__ bxyz, const float* __restrict__ wmlp) {
    extern __shared__ char smc[];
    uint32_t smb = smem_u32(smc);
    int t = threadIdx.x;
    int warp = t >> 5, lane = t & 31;
    int wm = warp & 7, wn = warp >> 3;

    // ---- zero W + G areas (pad columns must be 0) ----
    for (uint32_t off = (uint32_t)t * 16; off < SMEM_TOTAL; off += 512u * 16)
        *(uint4*)(smc + off) = make_uint4(0, 0, 0, 0);
    __syncthreads();

    // ---- W -> smem fp16, K-permuted: feats at 0..127, xyz at 128..130 ----
    for (int idx = t; idx < 256 * 131; idx += 512) {
        int o = idx / 131, k = idx % 131;
        int kk = (k < 3) ? (128 + k) : (k - 3);
        *(__half*)(smc + OFF_W + o * WPITCH + kk * 2) =
            __float2half_rn(wmlp[o * 131 + k]);
    }

    // ---- ldmatrix per-thread address components ----
    int sub = lane & 7, grp = lane >> 3;
    int rowA = sub + 8 * (grp & 1);  uint32_t kA2 = (uint32_t)(grp >> 1) * 16;
    int rowB = sub + 8 * (grp >> 1); uint32_t kB2 = (uint32_t)(grp & 1) * 16;
    uint32_t aHi0 = smb + OFF_W + (uint32_t)(wm * 32 + rowA) * WPITCH + kA2;
    uint32_t aHi1 = aHi0 + 16 * WPITCH;
    uint32_t bRow = (uint32_t)(wn * 32 + rowB) * WPITCH + kB2;

    // ---- prologue: async gather of first group into buffer 0 ----
    gather_async(smb, smc, blockIdx.x, 0, warp, lane, t, bxyz);
    CPASYNC_COMMIT();
    CPASYNC_WAIT0();
    __syncthreads();

    // ---- hoist A (W) fragments ks 0..7 into registers (loop-invariant) ----
    uint32_t ah[64];
#pragma unroll
    for (int ks = 0; ks < 8; ks++) {
        ldsm4(&ah[ks * 8 + 0], aHi0 + (uint32_t)ks * 32);
        ldsm4(&ah[ks * 8 + 4], aHi1 + (uint32_t)ks * 32);
    }

    float sums[4] = {0.f, 0.f, 0.f, 0.f}, sqs[4] = {0.f, 0.f, 0.f, 0.f};
    int it = 0;
    for (int g = blockIdx.x; g < NG2; g += gridDim.x, it++) {
        int p = it & 1, pn = p ^ 1;

        // ---- issue next group's gather (lands during MMA) ----
        int gn = g + gridDim.x;
        if (gn < NG2) gather_async(smb, smc, gn, pn, warp, lane, t, bxyz);
        CPASYNC_COMMIT();

        // ---- single-pass MMA over K=144 (9 K-steps) ----
        float acc[32];
#pragma unroll
        for (int j = 0; j < 32; j++) acc[j] = 0.f;

        uint32_t bBase = smb + OFF_G + (uint32_t)p * GBUF + bRow;
#pragma unroll
        for (int ks = 0; ks < 8; ks++) {
            uint32_t kb = (uint32_t)ks * 32;
            uint32_t bh[8];
            ldsm4(&bh[0], bBase + kb);
            ldsm4(&bh[4], bBase + 16 * WPITCH + kb);
#pragma unroll
            for (int m = 0; m < 2; m++)
#pragma unroll
                for (int n = 0; n < 4; n++) {
                    int bi = 4 * (n >> 1) + 2 * (n & 1);
                    mma16816(&acc[m * 16 + 4 * n], &ah[ks * 8 + 4 * m], &bh[bi]);
                }
        }
        {   // ks = 8 (xyz + pad), A from smem
            uint32_t a8[8], bh[8];
            ldsm4(&a8[0], aHi0 + 256);
            ldsm4(&a8[4], aHi1 + 256);
            ldsm4(&bh[0], bBase + 256);
            ldsm4(&bh[4], bBase + 16 * WPITCH + 256);
#pragma unroll
            for (int m = 0; m < 2; m++)
#pragma unroll
                for (int n = 0; n < 4; n++) {
                    int bi = 4 * (n >> 1) + 2 * (n & 1);
                    mma16816(&acc[m * 16 + 4 * n], &a8[4 * m], &bh[bi]);
                }
        }

        // ---- epilogue: max + sum + sumsq ----
        float mxq[4];
#pragma unroll
        for (int k = 0; k < 4; k++) mxq[k] = -INFINITY;
#pragma unroll
        for (int k = 0; k < 4; k++) {
            int m = k >> 1, ds = k & 1;
#pragma unroll
            for (int na = 0; na < 4; na++)
#pragma unroll
                for (int e = 0; e < 2; e++) {
                    float v = acc[m * 16 + na * 4 + ds * 2 + e];
                    mxq[k] = fmaxf(mxq[k], v);
                    sums[k] += v;
                    sqs[k] = fmaf(v, v, sqs[k]);
                }
        }
#pragma unroll
        for (int k = 0; k < 4; k++) {
            float mx = mxq[k];
            mx = fmaxf(mx, __shfl_xor_sync(0xffffffffu, mx, 1));
            mx = fmaxf(mx, __shfl_xor_sync(0xffffffffu, mx, 2));
            if ((lane & 3) == 0) {
                int o = wm * 32 + 16 * (k >> 1) + (lane >> 2) + 8 * (k & 1);
                d_mx[(size_t)(g * 2 + wn) * COUT + o] = mx;
            }
        }

        CPASYNC_WAIT0();
        __syncthreads();
    }

    // ---- flush channel sums ----
#pragma unroll
    for (int k = 0; k < 4; k++) {
        float s_ = sums[k], q_ = sqs[k];
        s_ += __shfl_xor_sync(0xffffffffu, s_, 1);
        s_ += __shfl_xor_sync(0xffffffffu, s_, 2);
        q_ += __shfl_xor_sync(0xffffffffu, q_, 1);
        q_ += __shfl_xor_sync(0xffffffffu, q_, 2);
        if ((lane & 3) == 0) {
            int o = wm * 32 + 16 * (k >> 1) + (lane >> 2) + 8 * (k & 1);
            atomicAdd(&d_sums[o],        (double)s_);
            atomicAdd(&d_sums[COUT + o], (double)q_);
        }
    }
}

// ---------------- kernel 4: finalize (affine computed in-block; gamma > 0) ----------
__global__ void k_finalize(const float* __restrict__ gamma,
                           const float* __restrict__ beta,
                           float* __restrict__ out) {
    __shared__ float aff[2 * COUT];
    int t = threadIdx.x;
    {
        double m = d_sums[t] / MLPCNT;
        double v = d_sums[COUT + t] / MLPCNT - m * m;
        float a  = gamma[t] * rsqrtf((float)v + EPSB);
        aff[t]        = a;
        aff[COUT + t] = beta[t] - (float)m * a;
    }
    __syncthreads();
    size_t i4 = (size_t)blockIdx.x * 256 + t;
    int o = (t * 4) & 255;
    float4 v = ((const float4*)d_mx)[i4];
    float4 r;
    r.x = fmaxf(aff[o+0] * v.x + aff[COUT+o+0], 0.0f);
    r.y = fmaxf(aff[o+1] * v.y + aff[COUT+o+1], 0.0f);
    r.z = fmaxf(aff[o+2] * v.z + aff[COUT+o+2], 0.0f);
    r.w = fmaxf(aff[o+3] * v.w + aff[COUT+o+3], 0.0f);
    ((float4*)out)[i4] = r;
}

// ---------------- launch ----------------
extern "C" void kernel_launch(void* const* d_in, const int* in_sizes, int n_in,
                              void* d_out, int out_size) {
    const float* ffps  = (const float*)d_in[0];
    const float* bxyz  = (const float*)d_in[1];
    const float* feats = (const float*)d_in[2];
    const float* wsh   = (const float*)d_in[3];
    const float* gsh   = (const float*)d_in[4];
    const float* bsh   = (const float*)d_in[5];
    const float* wmlp  = (const float*)d_in[6];
    const float* gmlp  = (const float*)d_in[7];
    const float* bmlp  = (const float*)d_in[8];
    float* out = (float*)d_out;

    cudaFuncSetAttribute(k_mlp, cudaFuncAttributeMaxDynamicSharedMemorySize, SMEM_TOTAL);

    k_zero_stats<<<1, 512>>>();
    k_shift_stats<<<NQ / 256, 256>>>(ffps, wsh);
    k_prep<<<2048, 256>>>(feats, bxyz, ffps, wsh, gsh, bsh);
    k_mlp<<<152, 512, SMEM_TOTAL>>>(bxyz, wmlp);
    k_finalize<<<NQ * COUT / 1024, 256>>>(gmlp, bmlp, out);
}

// round 17
// speedup vs baseline: 1.0939x; 1.0185x over previous
#include <cuda_runtime.h>
#include <cuda_fp16.h>
#include <cstdint>
#include <math.h>

// ---------------- problem constants ----------------
#define B     4
#define N     8192
#define P     2048
#define C     128
#define COUT  256
#define S     32
#define R2    0.64f
#define EPSB  1e-5f

#define NQ    (B*P)          // 8192 queries
#define NG2   (NQ/2)         // 4096 groups of 2 queries (64 samples)
#define MLPCNT ((double)(B)*(double)(P)*(double)(S))

// smem layout (bytes). Pitch 304 B (152 halves): conflict-free ldmatrix.
// K: 0..127 feats, 128..130 xyz, 131..143 zero pad.
#define WPITCH  304
#define OFF_W   0                     // W fp16 [256][152]  77824 B
#define OFF_G   77824                 // 2 bufs x G[64][152] = 2 x 19456
#define GBUF    19456
#define SMEM_TOTAL (77824 + 2*19456)  // 116736

// ---------------- device scratch ----------------
__device__ float          d_newxyz[NQ * 3];
__device__ int            d_idx[NQ * S];
__device__ unsigned short d_fhi[(size_t)B * N * C];   // fp16 of featsT (B,N,C)
__device__ float          d_mx[NQ * COUT];
__device__ double         d_sums[2 * COUT];
__device__ double         d_sst[6];
__device__ int            d_done;

// ---------------- PTX helpers ----------------
__device__ __forceinline__ uint32_t smem_u32(const void* p) {
    uint32_t a;
    asm("{ .reg .u64 t; cvta.to.shared.u64 t, %1; cvt.u32.u64 %0, t; }" : "=r"(a) : "l"(p));
    return a;
}
__device__ __forceinline__ void ldsm4(uint32_t* r, uint32_t addr) {
    asm volatile("ldmatrix.sync.aligned.m8n8.x4.shared.b16 {%0,%1,%2,%3}, [%4];"
                 : "=r"(r[0]), "=r"(r[1]), "=r"(r[2]), "=r"(r[3]) : "r"(addr));
}
__device__ __forceinline__ void mma16816(float* d, const uint32_t* a, const uint32_t* b) {
    asm volatile("mma.sync.aligned.m16n8k16.row.col.f32.f16.f16.f32 "
                 "{%0,%1,%2,%3}, {%4,%5,%6,%7}, {%8,%9}, {%0,%1,%2,%3};"
                 : "+f"(d[0]), "+f"(d[1]), "+f"(d[2]), "+f"(d[3])
                 : "r"(a[0]), "r"(a[1]), "r"(a[2]), "r"(a[3]), "r"(b[0]), "r"(b[1]));
}
__device__ __forceinline__ void cpa16(uint32_t dst, const void* src) {
    asm volatile("cp.async.cg.shared.global [%0], [%1], 16;" :: "r"(dst), "l"(src) : "memory");
}
#define CPASYNC_COMMIT() asm volatile("cp.async.commit_group;" ::: "memory")
#define CPASYNC_WAIT0()  asm volatile("cp.async.wait_group 0;" ::: "memory")

// ---------------- kernel 1: init + shift BN stats (single block, no atomics) ------
__global__ void k_stats(const float* __restrict__ ffps,
                        const float* __restrict__ wsh) {
    __shared__ double red[32][6];
    int t = threadIdx.x;                     // 1024 threads
    if (t < 2 * COUT) d_sums[t] = 0.0;
    if (t == 0)       d_done = 0;

    float w[9];
#pragma unroll
    for (int j = 0; j < 9; j++) w[j] = wsh[j];

    float xs[3] = {0.f, 0.f, 0.f}, xq[3] = {0.f, 0.f, 0.f};
    for (int i = t; i < NQ; i += 1024) {
        float f0 = ffps[i*3+0], f1 = ffps[i*3+1], f2 = ffps[i*3+2];
#pragma unroll
        for (int o = 0; o < 3; o++) {
            float x = w[o*3+0]*f0 + w[o*3+1]*f1 + w[o*3+2]*f2;
            xs[o] += x; xq[o] += x * x;
        }
    }
#pragma unroll
    for (int off = 16; off > 0; off >>= 1) {
#pragma unroll
        for (int o = 0; o < 3; o++) {
            xs[o] += __shfl_down_sync(0xffffffffu, xs[o], off);
            xq[o] += __shfl_down_sync(0xffffffffu, xq[o], off);
        }
    }
    int warp = t >> 5, lane = t & 31;
    if (lane == 0) {
#pragma unroll
        for (int o = 0; o < 3; o++) {
            red[warp][o]     = (double)xs[o];
            red[warp][3 + o] = (double)xq[o];
        }
    }
    __syncthreads();
    if (t < 6) {
        double s = 0.0;
#pragma unroll
        for (int wdx = 0; wdx < 32; wdx++) s += red[wdx][t];
        d_sst[t] = s;
    }
}

// ---------------- kernel 2: fused prep ----------------
// blocks [0, 1024): ball query (launched FIRST -> long scans start in wave 1)
// blocks [1024, 2048): feature transpose, 128(N) x 32(C) tiles, float4 loads
__global__ void k_prep(const float* __restrict__ f,
                       const float* __restrict__ bxyz,
                       const float* __restrict__ ffps,
                       const float* __restrict__ wsh,
                       const float* __restrict__ gamma,
                       const float* __restrict__ beta) {
    if (blockIdx.x >= 1024) {
        // ---------- transpose part: (B,C,N) fp32 -> (B,N,C) fp16 ----------
        __shared__ float tile[32][133];
        int bid = blockIdx.x - 1024;
        int lane = threadIdx.x & 31, warp = threadIdx.x >> 5;
        int b  = bid >> 8;
        int c0 = ((bid >> 6) & 3) * 32;
        int n0 = (bid & 63) * 128;
        const float* src = f + ((size_t)b * C + c0) * N + n0;
#pragma unroll
        for (int r = warp; r < 32; r += 8) {
            float4 v = ((const float4*)(src + (size_t)r * N))[lane];
            tile[r][lane * 4 + 0] = v.x;
            tile[r][lane * 4 + 1] = v.y;
            tile[r][lane * 4 + 2] = v.z;
            tile[r][lane * 4 + 3] = v.w;
        }
        __syncthreads();
        size_t base = ((size_t)b * N + n0) * C + c0;
        int nn = warp * 2 + (lane >> 4);
        int cc = (lane & 15) * 2;
#pragma unroll
        for (int pass = 0; pass < 8; pass++) {
            int n = nn + pass * 16;
            __half2 h = __floats2half2_rn(tile[cc][n], tile[cc + 1][n]);
            *(__half2*)(d_fhi + base + (size_t)n * C + cc) = h;
        }
        return;
    }

    // ---------- ball query part ----------
    int wid  = blockIdx.x * 8 + (threadIdx.x >> 5);
    int lane = threadIdx.x & 31;
    int b = wid >> 11;

    float cen[3];
    {
        const float* fp = ffps + (size_t)wid * 3;
        float f0 = fp[0], f1 = fp[1], f2 = fp[2];
        double cnt = (double)NQ;
#pragma unroll
        for (int o = 0; o < 3; o++) {
            float x = wsh[o*3+0]*f0 + wsh[o*3+1]*f1 + wsh[o*3+2]*f2;
            double m = d_sst[o] / cnt;
            double v = d_sst[3+o] / cnt - m * m;
            float a = gamma[o] * rsqrtf((float)v + EPSB);
            cen[o] = fmaxf((x - (float)m) * a + beta[o], 0.0f);
        }
    }
    if (lane == 0) {
        d_newxyz[wid*3+0] = cen[0];
        d_newxyz[wid*3+1] = cen[1];
        d_newxyz[wid*3+2] = cen[2];
    }

    int* outp = d_idx + (size_t)wid * S;

    // distance lower bound: points strictly inside [-1,1); cen >= 0
    {
        float e0 = fmaxf(cen[0] - 1.0f, 0.0f);
        float e1 = fmaxf(cen[1] - 1.0f, 0.0f);
        float e2 = fmaxf(cen[2] - 1.0f, 0.0f);
        if (e0*e0 + e1*e1 + e2*e2 >= R2) {
            if (lane < S) outp[lane] = 0;
            return;
        }
    }

    const float* xb = bxyz + (size_t)b * N * 3;
    int cnt = 0, first = 0;
    bool found = false;
    for (int n0 = 0; n0 < N && cnt < S; n0 += 128) {
        float d2v[4];
#pragma unroll
        for (int j = 0; j < 4; j++) {
            int n = n0 + j * 32 + lane;
            float dx = xb[n*3+0] - cen[0];
            float dy = xb[n*3+1] - cen[1];
            float dz = xb[n*3+2] - cen[2];
            d2v[j] = dx*dx + dy*dy + dz*dz;
        }
#pragma unroll
        for (int j = 0; j < 4; j++) {
            unsigned m = __ballot_sync(0xffffffffu, d2v[j] < R2);
            if (m) {
                if (!found) { found = true; first = n0 + j * 32 + __ffs(m) - 1; }
                bool hit = (m >> lane) & 1u;
                int pos = cnt + __popc(m & ((1u << lane) - 1u));
                if (hit && pos < S) outp[pos] = n0 + j * 32 + lane;
                cnt += __popc(m);
            }
        }
    }
    if (cnt > S) cnt = S;
    for (int s = cnt + lane; s < S; s += 32) outp[s] = first;
}

// ---- async gather of group gg into buffer pb ----
__device__ __forceinline__ void gather_async(uint32_t smb, char* smc,
                                             int gg, int pb,
                                             int warp, int lane, int t,
                                             const float* bxyz) {
    const int* idxp = d_idx + (size_t)gg * 64;
    int bb = gg >> 10;
    int l16 = lane & 15, hh = lane >> 4;
#pragma unroll
    for (int j = 0; j < 2; j++) {
        int s = warp * 4 + 2 * j + hh;
        int n = idxp[s];
        const char* src = (const char*)(d_fhi + ((size_t)bb * N + n) * C) + l16 * 16;
        cpa16(smb + OFF_G + (uint32_t)pb * GBUF + (uint32_t)s * WPITCH + (uint32_t)l16 * 16, src);
    }
    if (t < 64) {
        int n = idxp[t];
        int q = gg * 2 + (t >> 5);
        const float* cen = d_newxyz + (size_t)q * 3;
        const float* xp  = bxyz + ((size_t)bb * N + n) * 3;
        __half hx = __float2half_rn(xp[0] - cen[0]);
        __half hy = __float2half_rn(xp[1] - cen[1]);
        __half hz = __float2half_rn(xp[2] - cen[2]);
        char* dst = smc + OFF_G + (size_t)pb * GBUF + (size_t)t * WPITCH + 256;
        uint32_t xy = (uint32_t)__half_as_ushort(hx) |
                      ((uint32_t)__half_as_ushort(hy) << 16);
        *(uint32_t*)dst = xy;                   // k=128,129
        *(__half*)(dst + 4) = hz;               // k=130
    }
}

// ---------------- kernel 3: persistent HMMA MLP + fused finalize ----------------
// FROZEN R12 mainloop (73 us). Tail: grid-wide arrive/spin (all CTAs resident:
// grid == SM count, 1 CTA/SM), then grid-strided BN-affine + ReLU on L2-hot d_mx.
__global__ __launch_bounds__(512, 1)
void k_mlp(const float* __restrict__ bxyz, const float* __restrict__ wmlp,
           const float* __restrict__ gamma, const float* __restrict__ beta,
           float* __restrict__ out) {
    extern __shared__ char smc[];
    uint32_t smb = smem_u32(smc);
    int t = threadIdx.x;
    int warp = t >> 5, lane = t & 31;
    int wm = warp & 7, wn = warp >> 3;

    // ---- zero W + G areas (pad columns must be 0) ----
    for (uint32_t off = (uint32_t)t * 16; off < SMEM_TOTAL; off += 512u * 16)
        *(uint4*)(smc + off) = make_uint4(0, 0, 0, 0);
    __syncthreads();

    // ---- W -> smem fp16, K-permuted: feats at 0..127, xyz at 128..130 ----
    for (int idx = t; idx < 256 * 131; idx += 512) {
        int o = idx / 131, k = idx % 131;
        int kk = (k < 3) ? (128 + k) : (k - 3);
        *(__half*)(smc + OFF_W + o * WPITCH + kk * 2) =
            __float2half_rn(wmlp[o * 131 + k]);
    }

    // ---- ldmatrix per-thread address components ----
    int sub = lane & 7, grp = lane >> 3;
    int rowA = sub + 8 * (grp & 1);  uint32_t kA2 = (uint32_t)(grp >> 1) * 16;
    int rowB = sub + 8 * (grp >> 1); uint32_t kB2 = (uint32_t)(grp & 1) * 16;
    uint32_t aHi0 = smb + OFF_W + (uint32_t)(wm * 32 + rowA) * WPITCH + kA2;
    uint32_t aHi1 = aHi0 + 16 * WPITCH;
    uint32_t bRow = (uint32_t)(wn * 32 + rowB) * WPITCH + kB2;

    // ---- prologue: async gather of first group into buffer 0 ----
    gather_async(smb, smc, blockIdx.x, 0, warp, lane, t, bxyz);
    CPASYNC_COMMIT();
    CPASYNC_WAIT0();
    __syncthreads();

    // ---- hoist A (W) fragments ks 0..7 into registers (loop-invariant) ----
    uint32_t ah[64];
#pragma unroll
    for (int ks = 0; ks < 8; ks++) {
        ldsm4(&ah[ks * 8 + 0], aHi0 + (uint32_t)ks * 32);
        ldsm4(&ah[ks * 8 + 4], aHi1 + (uint32_t)ks * 32);
    }

    float sums[4] = {0.f, 0.f, 0.f, 0.f}, sqs[4] = {0.f, 0.f, 0.f, 0.f};
    int it = 0;
    for (int g = blockIdx.x; g < NG2; g += gridDim.x, it++) {
        int p = it & 1, pn = p ^ 1;

        // ---- issue next group's gather (lands during MMA) ----
        int gn = g + gridDim.x;
        if (gn < NG2) gather_async(smb, smc, gn, pn, warp, lane, t, bxyz);
        CPASYNC_COMMIT();

        // ---- single-pass MMA over K=144 (9 K-steps) ----
        float acc[32];
#pragma unroll
        for (int j = 0; j < 32; j++) acc[j] = 0.f;

        uint32_t bBase = smb + OFF_G + (uint32_t)p * GBUF + bRow;
#pragma unroll
        for (int ks = 0; ks < 8; ks++) {
            uint32_t kb = (uint32_t)ks * 32;
            uint32_t bh[8];
            ldsm4(&bh[0], bBase + kb);
            ldsm4(&bh[4], bBase + 16 * WPITCH + kb);
#pragma unroll
            for (int m = 0; m < 2; m++)
#pragma unroll
                for (int n = 0; n < 4; n++) {
                    int bi = 4 * (n >> 1) + 2 * (n & 1);
                    mma16816(&acc[m * 16 + 4 * n], &ah[ks * 8 + 4 * m], &bh[bi]);
                }
        }
        {   // ks = 8 (xyz + pad), A from smem
            uint32_t a8[8], bh[8];
            ldsm4(&a8[0], aHi0 + 256);
            ldsm4(&a8[4], aHi1 + 256);
            ldsm4(&bh[0], bBase + 256);
            ldsm4(&bh[4], bBase + 16 * WPITCH + 256);
#pragma unroll
            for (int m = 0; m < 2; m++)
#pragma unroll
                for (int n = 0; n < 4; n++) {
                    int bi = 4 * (n >> 1) + 2 * (n & 1);
                    mma16816(&acc[m * 16 + 4 * n], &a8[4 * m], &bh[bi]);
                }
        }

        // ---- epilogue: max + sum + sumsq ----
        float mxq[4];
#pragma unroll
        for (int k = 0; k < 4; k++) mxq[k] = -INFINITY;
#pragma unroll
        for (int k = 0; k < 4; k++) {
            int m = k >> 1, ds = k & 1;
#pragma unroll
            for (int na = 0; na < 4; na++)
#pragma unroll
                for (int e = 0; e < 2; e++) {
                    float v = acc[m * 16 + na * 4 + ds * 2 + e];
                    mxq[k] = fmaxf(mxq[k], v);
                    sums[k] += v;
                    sqs[k] = fmaf(v, v, sqs[k]);
                }
        }
#pragma unroll
        for (int k = 0; k < 4; k++) {
            float mx = mxq[k];
            mx = fmaxf(mx, __shfl_xor_sync(0xffffffffu, mx, 1));
            mx = fmaxf(mx, __shfl_xor_sync(0xffffffffu, mx, 2));
            if ((lane & 3) == 0) {
                int o = wm * 32 + 16 * (k >> 1) + (lane >> 2) + 8 * (k & 1);
                d_mx[(size_t)(g * 2 + wn) * COUT + o] = mx;
            }
        }

        CPASYNC_WAIT0();
        __syncthreads();
    }

    // ---- flush channel sums ----
#pragma unroll
    for (int k = 0; k < 4; k++) {
        float s_ = sums[k], q_ = sqs[k];
        s_ += __shfl_xor_sync(0xffffffffu, s_, 1);
        s_ += __shfl_xor_sync(0xffffffffu, s_, 2);
        q_ += __shfl_xor_sync(0xffffffffu, q_, 1);
        q_ += __shfl_xor_sync(0xffffffffu, q_, 2);
        if ((lane & 3) == 0) {
            int o = wm * 32 + 16 * (k >> 1) + (lane >> 2) + 8 * (k & 1);
            atomicAdd(&d_sums[o],        (double)s_);
            atomicAdd(&d_sums[COUT + o], (double)q_);
        }
    }

    // ---- grid-wide completion: all CTAs resident (grid == SM count) ----
    __threadfence();
    __syncthreads();
    if (t == 0) {
        atomicAdd(&d_done, 1);
        while (atomicAdd(&d_done, 0) < (int)gridDim.x)
            __nanosleep(64);
    }
    __syncthreads();
    __threadfence();

    // ---- fused finalize: BN affine + ReLU on L2-hot d_mx ----
    float* aff = (float*)smc;        // reuse smem (W no longer needed)
    if (t < COUT) {
        double m = d_sums[t] / MLPCNT;
        double v = d_sums[COUT + t] / MLPCNT - m * m;
        float a  = gamma[t] * rsqrtf((float)v + EPSB);
        aff[t]        = a;
        aff[COUT + t] = beta[t] - (float)m * a;
    }
    __syncthreads();
    int total4 = NQ * COUT / 4;
    for (int i = blockIdx.x * 512 + t; i < total4; i += gridDim.x * 512) {
        int o = (i * 4) & 255;
        float4 v = ((const float4*)d_mx)[i];
        float4 r;
        r.x = fmaxf(aff[o+0] * v.x + aff[COUT+o+0], 0.0f);
        r.y = fmaxf(aff[o+1] * v.y + aff[COUT+o+1], 0.0f);
        r.z = fmaxf(aff[o+2] * v.z + aff[COUT+o+2], 0.0f);
        r.w = fmaxf(aff[o+3] * v.w + aff[COUT+o+3], 0.0f);
        ((float4*)out)[i] = r;
    }
}

// ---------------- launch ----------------
extern "C" void kernel_launch(void* const* d_in, const int* in_sizes, int n_in,
                              void* d_out, int out_size) {
    const float* ffps  = (const float*)d_in[0];
    const float* bxyz  = (const float*)d_in[1];
    const float* feats = (const float*)d_in[2];
    const float* wsh   = (const float*)d_in[3];
    const float* gsh   = (const float*)d_in[4];
    const float* bsh   = (const float*)d_in[5];
    const float* wmlp  = (const float*)d_in[6];
    const float* gmlp  = (const float*)d_in[7];
    const float* bmlp  = (const float*)d_in[8];
    float* out = (float*)d_out;

    int nsm = 148;
    cudaDeviceGetAttribute(&nsm, cudaDevAttrMultiProcessorCount, 0);
    if (nsm > 152) nsm = 152;

    cudaFuncSetAttribute(k_mlp, cudaFuncAttributeMaxDynamicSharedMemorySize, SMEM_TOTAL);

    k_stats<<<1, 1024>>>(ffps, wsh);
    k_prep<<<2048, 256>>>(feats, bxyz, ffps, wsh, gsh, bsh);
    k_mlp<<<nsm, 512, SMEM_TOTAL>>>(bxyz, wmlp, gmlp, bmlp, out);
}